// round 14
// baseline (speedup 1.0000x reference)
#include <cuda_runtime.h>

#define NB 4
#define NH 16
#define SEQ 2048
#define DIM 1024
#define HD 64
#define SCALE 0.03125f   // 1/sqrt(1024)

typedef unsigned int u32;

// Scratch (allocation-free rule: __device__ globals)
__device__ float g_linv[NB * NH * SEQ];
__device__ float g_att[(size_t)NB * SEQ * DIM];

// ---------------------------------------------------------------------------
// Low-level helpers (portable sm_80+ PTX)
// ---------------------------------------------------------------------------
__device__ __forceinline__ u32 bf16x2_rn(float hi, float lo) {
    u32 r; asm("cvt.rn.bf16x2.f32 %0, %1, %2;" : "=r"(r) : "f"(hi), "f"(lo)); return r;
}
__device__ __forceinline__ u32 f16x2_rn(float hi, float lo) {
    u32 r; asm("cvt.rn.f16x2.f32 %0, %1, %2;" : "=r"(r) : "f"(hi), "f"(lo)); return r;
}
__device__ __forceinline__ u32 ex2h2(u32 x) {     // 2 exps per MUFU op
    u32 r; asm("ex2.approx.f16x2 %0, %1;" : "=r"(r) : "r"(x)); return r;
}
__device__ __forceinline__ u32 haddx2(u32 a, u32 b) {
    u32 r; asm("add.f16x2 %0, %1, %2;" : "=r"(r) : "r"(a), "r"(b)); return r;
}
__device__ __forceinline__ float2 h2f2(u32 e) {
    float2 f;
    asm("{.reg .b16 h0,h1; mov.b32 {h0,h1}, %2; cvt.f32.f16 %0, h0; cvt.f32.f16 %1, h1;}"
        : "=f"(f.x), "=f"(f.y) : "r"(e));
    return f;
}

// m16n8k16 bf16 mma
__device__ __forceinline__ void mma16(float c[4], uint4 a, uint2 b) {
    asm volatile(
        "mma.sync.aligned.m16n8k16.row.col.f32.bf16.bf16.f32 "
        "{%0,%1,%2,%3}, {%4,%5,%6,%7}, {%8,%9}, {%0,%1,%2,%3};"
        : "+f"(c[0]), "+f"(c[1]), "+f"(c[2]), "+f"(c[3])
        : "r"(a.x), "r"(a.y), "r"(a.z), "r"(a.w), "r"(b.x), "r"(b.y));
}
// m16n8k16 fp16 mma
__device__ __forceinline__ void mma16f(float c[4], uint4 a, uint2 b) {
    asm volatile(
        "mma.sync.aligned.m16n8k16.row.col.f32.f16.f16.f32 "
        "{%0,%1,%2,%3}, {%4,%5,%6,%7}, {%8,%9}, {%0,%1,%2,%3};"
        : "+f"(c[0]), "+f"(c[1]), "+f"(c[2]), "+f"(c[3])
        : "r"(a.x), "r"(a.y), "r"(a.z), "r"(a.w), "r"(b.x), "r"(b.y));
}

// ---------------------------------------------------------------------------
// 16-bit fragment packs (m16n8k16). A-pack: [ks][mt(8)][lane] uint4.
// B-pack padded: [ks][nt][33 lane-pairs] uint2.
// ---------------------------------------------------------------------------
__device__ __forceinline__ uint4 ldA16(const u32* A, int ks, int mt, int lane) {
    return *(const uint4*)(A + ((size_t)((ks * 8 + mt) * 32 + lane)) * 4);
}
template<int NT>
__device__ __forceinline__ uint2 ldB16(const u32* B, int ks, int nt, int lane) {
    return *(const uint2*)(B + ((size_t)((ks * NT + nt) * 33 + lane)) * 2);
}
// bf16 stores (k1)
__device__ __forceinline__ void stA16_rn(u32* A, int r, int c4, float4 v) {
    int ks = c4 >> 4, kkb = c4 & 15;
    const float* f = &v.x;
#pragma unroll
    for (int p = 0; p < 2; p++) {
        int kk = kkb + 2 * p;
        int c = (kk & 7) >> 1, slot = ((r >> 3) & 1) | ((kk >> 3) << 1);
        int idx = ((ks * 8 + (r >> 4)) * 32 + ((r & 7) << 2) + c) * 4 + slot;
        A[idx] = bf16x2_rn(f[2 * p + 1], f[2 * p]);
    }
}
template<int NT>
__device__ __forceinline__ void stB16_rn(u32* B, int n, int c4, float4 v) {
    int ks = c4 >> 4, kkb = c4 & 15;
    const float* f = &v.x;
#pragma unroll
    for (int p = 0; p < 2; p++) {
        int kk = kkb + 2 * p;
        int c = (kk & 7) >> 1, breg = kk >> 3;
        int idx = ((ks * NT + (n >> 3)) * 33 + ((n & 7) << 2) + c) * 2 + breg;
        B[idx] = bf16x2_rn(f[2 * p + 1], f[2 * p]);
    }
}
// fp16 stores (k2/k3)
__device__ __forceinline__ void stA16f(u32* A, int r, int c4, float4 v) {
    int ks = c4 >> 4, kkb = c4 & 15;
    const float* f = &v.x;
#pragma unroll
    for (int p = 0; p < 2; p++) {
        int kk = kkb + 2 * p;
        int c = (kk & 7) >> 1, slot = ((r >> 3) & 1) | ((kk >> 3) << 1);
        int idx = ((ks * 8 + (r >> 4)) * 32 + ((r & 7) << 2) + c) * 4 + slot;
        A[idx] = f16x2_rn(f[2 * p + 1], f[2 * p]);
    }
}
template<int NT>
__device__ __forceinline__ void stB16f(u32* B, int n, int c4, float4 v) {
    int ks = c4 >> 4, kkb = c4 & 15;
    const float* f = &v.x;
#pragma unroll
    for (int p = 0; p < 2; p++) {
        int kk = kkb + 2 * p;
        int c = (kk & 7) >> 1, breg = kk >> 3;
        int idx = ((ks * NT + (n >> 3)) * 33 + ((n & 7) << 2) + c) * 2 + breg;
        B[idx] = f16x2_rn(f[2 * p + 1], f[2 * p]);
    }
}

// ---------------------------------------------------------------------------
// Kernel 1: l[k] = sum_q exp(s[q,k]); store 1/l.
// K pre-scaled by SCALE*log2(e) at pack time (no per-element FMUL);
// packed fp16 ex2 + fp16 pair-reduce before widening.
// ---------------------------------------------------------------------------
__global__ void __launch_bounds__(256) k1_colsum(const float* __restrict__ Qg,
                                                 const float* __restrict__ Kg) {
    extern __shared__ u32 smu[];
    u32* Ka = smu;                       // 4096 u32
    u32* Qb = smu + 4096;                // 4224 u32
    float* colsum = (float*)(smu + 8320);
    int tid = threadIdx.x, lane = tid & 31, w = tid >> 5;
    int wm = w >> 2, wn = w & 3;
    int b = blockIdx.z, h = blockIdx.y, k0 = blockIdx.x << 7;

    const float* Kb = Kg + ((size_t)b * SEQ + k0) * DIM + h * HD;
    const float* Qbase = Qg + (size_t)b * SEQ * DIM + h * HD;

    const float C2 = SCALE * 1.4426950408889634f;   // SCALE * log2(e)

    int rb = tid >> 4, c4 = (tid & 15) << 2;
#pragma unroll
    for (int it = 0; it < 8; it++) {
        int r = rb + (it << 4);
        float4 kv = *(const float4*)(Kb + (size_t)r * DIM + c4);
        kv.x *= C2; kv.y *= C2; kv.z *= C2; kv.w *= C2;
        stA16_rn(Ka, r, c4, kv);
    }
    if (tid < 128) colsum[tid] = 0.f;

    float sume[4][2];
#pragma unroll
    for (int i = 0; i < 4; i++) { sume[i][0] = 0.f; sume[i][1] = 0.f; }

    for (int q0 = 0; q0 < SEQ; q0 += 128) {
        __syncthreads();
#pragma unroll
        for (int it = 0; it < 8; it++) {
            int n = rb + (it << 4);
            stB16_rn<16>(Qb, n, c4,
                         *(const float4*)(Qbase + (size_t)(q0 + n) * DIM + c4));
        }
        __syncthreads();

        float acc[4][4][4];
#pragma unroll
        for (int i = 0; i < 4; i++)
#pragma unroll
            for (int j = 0; j < 4; j++)
#pragma unroll
                for (int t = 0; t < 4; t++) acc[i][j][t] = 0.f;

#pragma unroll
        for (int ks = 0; ks < 4; ks++) {
            uint4 af[4]; uint2 bf[4];
#pragma unroll
            for (int i = 0; i < 4; i++) af[i] = ldA16(Ka, ks, wm * 4 + i, lane);
#pragma unroll
            for (int j = 0; j < 4; j++) bf[j] = ldB16<16>(Qb, ks, wn * 4 + j, lane);
#pragma unroll
            for (int i = 0; i < 4; i++)
#pragma unroll
                for (int j = 0; j < 4; j++) mma16(acc[i][j], af[i], bf[j]);
        }
        // exp via packed fp16 ex2 (arg already scaled); pair-reduce in fp16
#pragma unroll
        for (int i = 0; i < 4; i++)
#pragma unroll
            for (int j = 0; j < 4; j += 2) {
                u32 e01a = ex2h2(f16x2_rn(acc[i][j][1], acc[i][j][0]));
                u32 e23a = ex2h2(f16x2_rn(acc[i][j][3], acc[i][j][2]));
                u32 e01b = ex2h2(f16x2_rn(acc[i][j + 1][1], acc[i][j + 1][0]));
                u32 e23b = ex2h2(f16x2_rn(acc[i][j + 1][3], acc[i][j + 1][2]));
                float2 f01 = h2f2(haddx2(e01a, e01b));
                float2 f23 = h2f2(haddx2(e23a, e23b));
                sume[i][0] += f01.x + f01.y;
                sume[i][1] += f23.x + f23.y;
            }
    }

#pragma unroll
    for (int i = 0; i < 4; i++)
#pragma unroll
        for (int hh = 0; hh < 2; hh++) {
            float v = sume[i][hh];
            v += __shfl_xor_sync(0xffffffffu, v, 1);
            v += __shfl_xor_sync(0xffffffffu, v, 2);
            if ((lane & 3) == 0)
                atomicAdd(&colsum[wm * 64 + i * 16 + (lane >> 2) + hh * 8], v);
        }
    __syncthreads();
    if (tid < 128)
        g_linv[((size_t)b * NH + h) * SEQ + k0 + tid] = 1.0f / colsum[tid];
}

// ---------------------------------------------------------------------------
// Kernel 2: out[q,:] = sum_k exp(s[q,k]) * (linv[k]*v[k,:]).
// r11 math; Q pre-scaled by SCALE at pack time; gemm1 quarter-split
// (acc[4][4]) + launch_bounds(256,3) for 3 CTAs/SM. o-accumulation order
// is identical to r11 (same ks2 sequence).
// ---------------------------------------------------------------------------
__global__ void __launch_bounds__(256, 3) k2_attnv(const float* __restrict__ Qg,
                                                   const float* __restrict__ Kg,
                                                   const float* __restrict__ Vg) {
    extern __shared__ u32 smu[];
    u32* Qa = smu;              // fp16 A-pack 128q x 64d : 4096 u32
    u32* Kp = smu + 4096;       // fp16 B-pack 128k x 64d : 4224 u32
    u32* Vp = smu + 8320;       // fp16 B-pack 128k x 64d : 4224 u32
    float* Tsc = (float*)(smu + 12544);   // 256x4 partial T : 1024 u32
    float* Tf  = (float*)(smu + 13568);   // reduced T[64]
    // total 13632 u32 = 54528 B -> 3 CTAs/SM by smem

    int tid = threadIdx.x, lane = tid & 31, w = tid >> 5;
    int b = blockIdx.z, h = blockIdx.y, q0 = blockIdx.x << 7;

    const float* Qb = Qg + ((size_t)b * SEQ + q0) * DIM + h * HD;
    const float* Kbase = Kg + (size_t)b * SEQ * DIM + h * HD;
    const float* Vbase = Vg + (size_t)b * SEQ * DIM + h * HD;
    const float* linv = g_linv + ((size_t)b * NH + h) * SEQ;

    int rb = tid >> 4, c4 = (tid & 15) << 2;
#pragma unroll
    for (int it = 0; it < 8; it++) {
        int r = rb + (it << 4);
        float4 qv = *(const float4*)(Qb + (size_t)r * DIM + c4);
        qv.x *= SCALE; qv.y *= SCALE; qv.z *= SCALE; qv.w *= SCALE;
        stA16f(Qa, r, c4, qv);
    }

    float o[8][4];
#pragma unroll
    for (int nt = 0; nt < 8; nt++)
#pragma unroll
        for (int t = 0; t < 4; t++) o[nt][t] = 0.f;
    float Tl[4] = {0.f, 0.f, 0.f, 0.f};

    for (int k0 = 0; k0 < SEQ; k0 += 128) {
        __syncthreads();
#pragma unroll
        for (int it = 0; it < 8; it++) {
            int n = rb + (it << 4);
            stB16f<16>(Kp, n, c4,
                       *(const float4*)(Kbase + (size_t)(k0 + n) * DIM + c4));
        }
#pragma unroll
        for (int it = 0; it < 8; it++) {
            int kt = rb + (it << 4);
            float rl = __ldg(linv + k0 + kt) * 1024.0f;
            float4 v = *(const float4*)(Vbase + (size_t)(k0 + kt) * DIM + c4);
            v.x *= rl; v.y *= rl; v.z *= rl; v.w *= rl;
            Tl[0] += v.x; Tl[1] += v.y; Tl[2] += v.z; Tl[3] += v.w;
            float4 oth;
            oth.x = __shfl_xor_sync(0xffffffffu, v.x, 16);
            oth.y = __shfl_xor_sync(0xffffffffu, v.y, 16);
            oth.z = __shfl_xor_sync(0xffffffffu, v.z, 16);
            oth.w = __shfl_xor_sync(0xffffffffu, v.w, 16);
            float4 ve, vo;
            if (lane & 16) { ve = oth; vo = v; } else { ve = v; vo = oth; }
            if (((lane >> 4) & 1) == (it & 1)) {
                int ke = kt & ~1;
                int ksv = ke >> 4, kk = ke & 15;
                int c = (kk & 7) >> 1, breg = kk >> 3;
                const float* pe = &ve.x; const float* po = &vo.x;
#pragma unroll
                for (int j = 0; j < 4; j++) {
                    int d = c4 + j;
                    int idx = ((ksv * 8 + (d >> 3)) * 33 + ((d & 7) << 2) + c) * 2 + breg;
                    Vp[idx] = f16x2_rn(po[j], pe[j]);
                }
            }
        }
        __syncthreads();

        // four 32-col k-chunks: gemm1 chunk -> (exp-1) -> gemm2 chunk
#pragma unroll
        for (int ch = 0; ch < 4; ch++) {
            float acc[4][4];
#pragma unroll
            for (int nt = 0; nt < 4; nt++)
#pragma unroll
                for (int tt = 0; tt < 4; tt++) acc[nt][tt] = 0.f;
#pragma unroll
            for (int ks = 0; ks < 4; ks++) {
                uint4 a = ldA16(Qa, ks, w, lane);
#pragma unroll
                for (int nt = 0; nt < 4; nt++) {
                    uint2 bf = ldB16<16>(Kp, ks, ch * 4 + nt, lane);
                    mma16f(acc[nt], a, bf);
                }
            }

#pragma unroll
            for (int j2 = 0; j2 < 2; j2++) {
                float e0 = __expf(acc[2 * j2][0]) - 1.0f;
                float e1 = __expf(acc[2 * j2][1]) - 1.0f;
                float e2 = __expf(acc[2 * j2][2]) - 1.0f;
                float e3 = __expf(acc[2 * j2][3]) - 1.0f;
                float e4 = __expf(acc[2 * j2 + 1][0]) - 1.0f;
                float e5 = __expf(acc[2 * j2 + 1][1]) - 1.0f;
                float e6 = __expf(acc[2 * j2 + 1][2]) - 1.0f;
                float e7 = __expf(acc[2 * j2 + 1][3]) - 1.0f;
                uint4 ah;
                ah.x = f16x2_rn(e1, e0);
                ah.y = f16x2_rn(e3, e2);
                ah.z = f16x2_rn(e5, e4);
                ah.w = f16x2_rn(e7, e6);
                int ks2 = ch * 2 + j2;
#pragma unroll
                for (int nt = 0; nt < 8; nt++) {
                    uint2 bv = ldB16<8>(Vp, ks2, nt, lane);
                    mma16f(o[nt], ah, bv);
                }
            }
        }
    }

    __syncthreads();
#pragma unroll
    for (int j = 0; j < 4; j++) Tsc[tid * 4 + j] = Tl[j];
    __syncthreads();
    if (tid < 64) {
        float s = 0.f;
#pragma unroll
        for (int r2 = 0; r2 < 16; r2++)
            s += Tsc[(r2 * 16 + (tid >> 2)) * 4 + (tid & 3)];
        Tf[tid] = s;
    }
    __syncthreads();

    const float inv1024 = 1.0f / 1024.0f;
    int r = lane >> 2, c2 = (lane & 3) << 1;
    float* obase = g_att + ((size_t)b * SEQ + q0 + 16 * w + r) * DIM + h * HD;
#pragma unroll
    for (int nt = 0; nt < 8; nt++) {
        int d0 = nt * 8 + c2;
        float t0 = Tf[d0], t1 = Tf[d0 + 1];
        *(float2*)(obase + d0) =
            make_float2((o[nt][0] + t0) * inv1024, (o[nt][1] + t1) * inv1024);
        *(float2*)(obase + (size_t)8 * DIM + d0) =
            make_float2((o[nt][2] + t0) * inv1024, (o[nt][3] + t1) * inv1024);
    }
}

// ---------------------------------------------------------------------------
// Kernel 3: out = g_att @ W^T + b.  Single-pass fp16. (r12, proven)
// ---------------------------------------------------------------------------
__global__ void __launch_bounds__(256, 2) k3_linear(const float* __restrict__ Wg,
                                                    const float* __restrict__ bg,
                                                    float* __restrict__ Og) {
    extern __shared__ u32 smu[];
    u32* Xp = smu;             // fp16 A-pack : 4096 u32
    u32* Wp = smu + 4096;      // fp16 B-pack : 4224 u32

    int tid = threadIdx.x, lane = tid & 31, w = tid >> 5;
    int wm = w >> 2, wn = w & 3;
    int n0 = blockIdx.x << 7, m0 = blockIdx.y << 7;

    float acc[4][4][4];
#pragma unroll
    for (int i = 0; i < 4; i++)
#pragma unroll
        for (int j = 0; j < 4; j++)
#pragma unroll
            for (int t = 0; t < 4; t++) acc[i][j][t] = 0.f;

    int rb = tid >> 4, c4 = (tid & 15) << 2;
    for (int d0 = 0; d0 < DIM; d0 += 64) {
        __syncthreads();
#pragma unroll
        for (int it = 0; it < 8; it++) {
            int r = rb + (it << 4);
            stA16f(Xp, r, c4,
                   *(const float4*)(g_att + (size_t)(m0 + r) * DIM + d0 + c4));
            stB16f<16>(Wp, r, c4,
                       *(const float4*)(Wg + (size_t)(n0 + r) * DIM + d0 + c4));
        }
        __syncthreads();

#pragma unroll
        for (int ks = 0; ks < 4; ks++) {
            uint4 ah[4]; uint2 bh[4];
#pragma unroll
            for (int i = 0; i < 4; i++) ah[i] = ldA16(Xp, ks, wm * 4 + i, lane);
#pragma unroll
            for (int j = 0; j < 4; j++) bh[j] = ldB16<16>(Wp, ks, wn * 4 + j, lane);
#pragma unroll
            for (int i = 0; i < 4; i++)
#pragma unroll
                for (int j = 0; j < 4; j++)
                    mma16f(acc[i][j], ah[i], bh[j]);
        }
    }

#pragma unroll
    for (int i = 0; i < 4; i++)
#pragma unroll
        for (int j = 0; j < 4; j++) {
            int r = wm * 64 + i * 16 + (lane >> 2);
            int n = wn * 32 + j * 8 + ((lane & 3) << 1);
            float2 bb = *(const float2*)(bg + n0 + n);
            float* p = Og + (size_t)(m0 + r) * DIM + n0 + n;
            *(float2*)p = make_float2(acc[i][j][0] + bb.x, acc[i][j][1] + bb.y);
            *(float2*)(p + (size_t)8 * DIM) =
                make_float2(acc[i][j][2] + bb.x, acc[i][j][3] + bb.y);
        }
}

// ---------------------------------------------------------------------------

extern "C" void kernel_launch(void* const* d_in, const int* in_sizes, int n_in,
                              void* d_out, int out_size) {
    const float* Q = (const float*)d_in[0];
    const float* K = (const float*)d_in[1];
    const float* V = (const float*)d_in[2];
    const float* W = (const float*)d_in[3];
    const float* bias = (const float*)d_in[4];
    float* out = (float*)d_out;
    (void)in_sizes; (void)n_in; (void)out_size;

    const int smem1 = (4096 + 4224 + 128) * 4;   // 33792
    const int smem2 = 13632 * 4;                 // 54528
    const int smem3 = 8320 * 4;                  // 33280

    cudaFuncSetAttribute(k1_colsum, cudaFuncAttributeMaxDynamicSharedMemorySize, smem1);
    cudaFuncSetAttribute(k2_attnv,  cudaFuncAttributeMaxDynamicSharedMemorySize, smem2);
    cudaFuncSetAttribute(k3_linear, cudaFuncAttributeMaxDynamicSharedMemorySize, smem3);

    dim3 gAttn(SEQ / 128, NH, NB);          // 1024 CTAs
    k1_colsum<<<gAttn, 256, smem1>>>(Q, K);
    k2_attnv<<<gAttn, 256, smem2>>>(Q, K, V);

    dim3 gLin(DIM / 128, (NB * SEQ) / 128); // 512 CTAs
    k3_linear<<<gLin, 256, smem3>>>(W, bias, out);
}

// round 15
// speedup vs baseline: 1.0532x; 1.0532x over previous
#include <cuda_runtime.h>

#define NB 4
#define NH 16
#define SEQ 2048
#define DIM 1024
#define HD 64
#define SCALE 0.03125f   // 1/sqrt(1024)

typedef unsigned int u32;

// Scratch (allocation-free rule: __device__ globals)
__device__ float g_att[(size_t)NB * SEQ * DIM];
__device__ u32 g_Kp[(size_t)NB * NH * 16 * 4224];   // fp16 K B-packs (per b,h,kblock)
__device__ u32 g_Vp[(size_t)NB * NH * 16 * 4224];   // fp16 V'' B-packs
__device__ float g_Tp[NB * NH * 16 * 64];           // per-kblock partial T

// ---------------------------------------------------------------------------
// Low-level helpers (portable sm_80+ PTX)
// ---------------------------------------------------------------------------
__device__ __forceinline__ u32 bf16x2_rn(float hi, float lo) {
    u32 r; asm("cvt.rn.bf16x2.f32 %0, %1, %2;" : "=r"(r) : "f"(hi), "f"(lo)); return r;
}
__device__ __forceinline__ u32 f16x2_rn(float hi, float lo) {
    u32 r; asm("cvt.rn.f16x2.f32 %0, %1, %2;" : "=r"(r) : "f"(hi), "f"(lo)); return r;
}
__device__ __forceinline__ u32 ex2h2(u32 x) {     // 2 exps per MUFU op
    u32 r; asm("ex2.approx.f16x2 %0, %1;" : "=r"(r) : "r"(x)); return r;
}
__device__ __forceinline__ float2 h2f2(u32 e) {
    float2 f;
    asm("{.reg .b16 h0,h1; mov.b32 {h0,h1}, %2; cvt.f32.f16 %0, h0; cvt.f32.f16 %1, h1;}"
        : "=f"(f.x), "=f"(f.y) : "r"(e));
    return f;
}

// m16n8k16 bf16 mma
__device__ __forceinline__ void mma16(float c[4], uint4 a, uint2 b) {
    asm volatile(
        "mma.sync.aligned.m16n8k16.row.col.f32.bf16.bf16.f32 "
        "{%0,%1,%2,%3}, {%4,%5,%6,%7}, {%8,%9}, {%0,%1,%2,%3};"
        : "+f"(c[0]), "+f"(c[1]), "+f"(c[2]), "+f"(c[3])
        : "r"(a.x), "r"(a.y), "r"(a.z), "r"(a.w), "r"(b.x), "r"(b.y));
}
// m16n8k16 fp16 mma
__device__ __forceinline__ void mma16f(float c[4], uint4 a, uint2 b) {
    asm volatile(
        "mma.sync.aligned.m16n8k16.row.col.f32.f16.f16.f32 "
        "{%0,%1,%2,%3}, {%4,%5,%6,%7}, {%8,%9}, {%0,%1,%2,%3};"
        : "+f"(c[0]), "+f"(c[1]), "+f"(c[2]), "+f"(c[3])
        : "r"(a.x), "r"(a.y), "r"(a.z), "r"(a.w), "r"(b.x), "r"(b.y));
}

// ---------------------------------------------------------------------------
// 16-bit fragment packs (m16n8k16). A-pack: [ks][mt(8)][lane] uint4.
// B-pack padded: [ks][nt][33 lane-pairs] uint2.
// ---------------------------------------------------------------------------
__device__ __forceinline__ uint4 ldA16(const u32* A, int ks, int mt, int lane) {
    return *(const uint4*)(A + ((size_t)((ks * 8 + mt) * 32 + lane)) * 4);
}
template<int NT>
__device__ __forceinline__ uint2 ldB16(const u32* B, int ks, int nt, int lane) {
    return *(const uint2*)(B + ((size_t)((ks * NT + nt) * 33 + lane)) * 2);
}
// bf16 stores (k1)
__device__ __forceinline__ void stA16_rn(u32* A, int r, int c4, float4 v) {
    int ks = c4 >> 4, kkb = c4 & 15;
    const float* f = &v.x;
#pragma unroll
    for (int p = 0; p < 2; p++) {
        int kk = kkb + 2 * p;
        int c = (kk & 7) >> 1, slot = ((r >> 3) & 1) | ((kk >> 3) << 1);
        int idx = ((ks * 8 + (r >> 4)) * 32 + ((r & 7) << 2) + c) * 4 + slot;
        A[idx] = bf16x2_rn(f[2 * p + 1], f[2 * p]);
    }
}
template<int NT>
__device__ __forceinline__ void stB16_rn(u32* B, int n, int c4, float4 v) {
    int ks = c4 >> 4, kkb = c4 & 15;
    const float* f = &v.x;
#pragma unroll
    for (int p = 0; p < 2; p++) {
        int kk = kkb + 2 * p;
        int c = (kk & 7) >> 1, breg = kk >> 3;
        int idx = ((ks * NT + (n >> 3)) * 33 + ((n & 7) << 2) + c) * 2 + breg;
        B[idx] = bf16x2_rn(f[2 * p + 1], f[2 * p]);
    }
}
// fp16 stores
__device__ __forceinline__ void stA16f(u32* A, int r, int c4, float4 v) {
    int ks = c4 >> 4, kkb = c4 & 15;
    const float* f = &v.x;
#pragma unroll
    for (int p = 0; p < 2; p++) {
        int kk = kkb + 2 * p;
        int c = (kk & 7) >> 1, slot = ((r >> 3) & 1) | ((kk >> 3) << 1);
        int idx = ((ks * 8 + (r >> 4)) * 32 + ((r & 7) << 2) + c) * 4 + slot;
        A[idx] = f16x2_rn(f[2 * p + 1], f[2 * p]);
    }
}
template<int NT>
__device__ __forceinline__ void stB16f(u32* B, int n, int c4, float4 v) {
    int ks = c4 >> 4, kkb = c4 & 15;
    const float* f = &v.x;
#pragma unroll
    for (int p = 0; p < 2; p++) {
        int kk = kkb + 2 * p;
        int c = (kk & 7) >> 1, breg = kk >> 3;
        int idx = ((ks * NT + (n >> 3)) * 33 + ((n & 7) << 2) + c) * 2 + breg;
        B[idx] = f16x2_rn(f[2 * p + 1], f[2 * p]);
    }
}

// ---------------------------------------------------------------------------
// Kernel 1: per (b,h,kblock):
//   (a) write fp16 K B-pack to g_Kp (for k2)
//   (b) colsum l[k] = sum_q exp(s[q,k])  (r13 math: bf16 mma + fp16 ex2)
//   (c) V'' = 1024*V/colsum -> fp16 B-pack to g_Vp; partial T to g_Tp
// ---------------------------------------------------------------------------
__global__ void __launch_bounds__(256) k1_colsum(const float* __restrict__ Qg,
                                                 const float* __restrict__ Kg,
                                                 const float* __restrict__ Vg) {
    extern __shared__ u32 smu[];
    u32* Ka = smu;                        // 4096 u32
    u32* Qb = smu + 4096;                 // 4224 u32
    float* colsum = (float*)(smu + 8320); // 128
    u32* Po = smu + 8448;                 // 4224 (K-pack out, then V-pack out)
    // total 12672 u32 = 50688 B

    int tid = threadIdx.x, lane = tid & 31, w = tid >> 5;
    int wm = w >> 2, wn = w & 3;
    int b = blockIdx.z, h = blockIdx.y, kb = blockIdx.x, k0 = kb << 7;

    const float* Kb = Kg + ((size_t)b * SEQ + k0) * DIM + h * HD;
    const float* Qbase = Qg + (size_t)b * SEQ * DIM + h * HD;
    const float* Vb = Vg + ((size_t)b * SEQ + k0) * DIM + h * HD;
    const size_t pbase = ((size_t)((b * NH + h) * 16 + kb)) * 4224;

    const float C2 = SCALE * 1.4426950408889634f;   // SCALE * log2(e)

    int rb = tid >> 4, c4 = (tid & 15) << 2;
#pragma unroll
    for (int it = 0; it < 8; it++) {
        int r = rb + (it << 4);
        float4 kv = *(const float4*)(Kb + (size_t)r * DIM + c4);
        stA16_rn(Ka, r, c4, kv);        // bf16 A-pack for own mma
        stB16f<16>(Po, r, c4, kv);      // fp16 B-pack for k2
    }
    if (tid < 128) colsum[tid] = 0.f;
    __syncthreads();
    // coalesced K-pack copy to gmem
    for (int i = tid; i < 1056; i += 256)
        ((uint4*)(g_Kp + pbase))[i] = ((const uint4*)Po)[i];

    float sume[4][2];
#pragma unroll
    for (int i = 0; i < 4; i++) { sume[i][0] = 0.f; sume[i][1] = 0.f; }

    for (int q0 = 0; q0 < SEQ; q0 += 128) {
        __syncthreads();
#pragma unroll
        for (int it = 0; it < 8; it++) {
            int n = rb + (it << 4);
            stB16_rn<16>(Qb, n, c4,
                         *(const float4*)(Qbase + (size_t)(q0 + n) * DIM + c4));
        }
        __syncthreads();

        float acc[4][4][4];
#pragma unroll
        for (int i = 0; i < 4; i++)
#pragma unroll
            for (int j = 0; j < 4; j++)
#pragma unroll
                for (int t = 0; t < 4; t++) acc[i][j][t] = 0.f;

#pragma unroll
        for (int ks = 0; ks < 4; ks++) {
            uint4 af[4]; uint2 bf[4];
#pragma unroll
            for (int i = 0; i < 4; i++) af[i] = ldA16(Ka, ks, wm * 4 + i, lane);
#pragma unroll
            for (int j = 0; j < 4; j++) bf[j] = ldB16<16>(Qb, ks, wn * 4 + j, lane);
#pragma unroll
            for (int i = 0; i < 4; i++)
#pragma unroll
                for (int j = 0; j < 4; j++) mma16(acc[i][j], af[i], bf[j]);
        }
#pragma unroll
        for (int i = 0; i < 4; i++)
#pragma unroll
            for (int j = 0; j < 4; j++) {
                u32 e01 = ex2h2(f16x2_rn(acc[i][j][1] * C2, acc[i][j][0] * C2));
                u32 e23 = ex2h2(f16x2_rn(acc[i][j][3] * C2, acc[i][j][2] * C2));
                float2 f01 = h2f2(e01);
                float2 f23 = h2f2(e23);
                sume[i][0] += f01.x + f01.y;
                sume[i][1] += f23.x + f23.y;
            }
    }

#pragma unroll
    for (int i = 0; i < 4; i++)
#pragma unroll
        for (int hh = 0; hh < 2; hh++) {
            float v = sume[i][hh];
            v += __shfl_xor_sync(0xffffffffu, v, 1);
            v += __shfl_xor_sync(0xffffffffu, v, 2);
            if ((lane & 3) == 0)
                atomicAdd(&colsum[wm * 64 + i * 16 + (lane >> 2) + hh * 8], v);
        }
    __syncthreads();

    // ---- V phase: V'' = 1024*V/colsum -> fp16 B-pack (NT=8) + partial T ----
    float Tl[4] = {0.f, 0.f, 0.f, 0.f};
#pragma unroll
    for (int it = 0; it < 8; it++) {
        int kt = rb + (it << 4);
        float rl = 1024.0f / colsum[kt];
        float4 v = *(const float4*)(Vb + (size_t)kt * DIM + c4);
        v.x *= rl; v.y *= rl; v.z *= rl; v.w *= rl;
        Tl[0] += v.x; Tl[1] += v.y; Tl[2] += v.z; Tl[3] += v.w;
        float4 oth;
        oth.x = __shfl_xor_sync(0xffffffffu, v.x, 16);
        oth.y = __shfl_xor_sync(0xffffffffu, v.y, 16);
        oth.z = __shfl_xor_sync(0xffffffffu, v.z, 16);
        oth.w = __shfl_xor_sync(0xffffffffu, v.w, 16);
        float4 ve, vo;
        if (lane & 16) { ve = oth; vo = v; } else { ve = v; vo = oth; }
        if (((lane >> 4) & 1) == (it & 1)) {
            int ke = kt & ~1;
            int ksv = ke >> 4, kk = ke & 15;
            int c = (kk & 7) >> 1, breg = kk >> 3;
            const float* pe = &ve.x; const float* po = &vo.x;
#pragma unroll
            for (int j = 0; j < 4; j++) {
                int d = c4 + j;
                int idx = ((ksv * 8 + (d >> 3)) * 33 + ((d & 7) << 2) + c) * 2 + breg;
                Po[idx] = f16x2_rn(po[j], pe[j]);
            }
        }
    }
    // partial-T scratch in Qb (free now)
    float* Tsc = (float*)Qb;
#pragma unroll
    for (int j = 0; j < 4; j++) Tsc[tid * 4 + j] = Tl[j];
    __syncthreads();
    for (int i = tid; i < 1056; i += 256)
        ((uint4*)(g_Vp + pbase))[i] = ((const uint4*)Po)[i];
    if (tid < 64) {
        float s = 0.f;
#pragma unroll
        for (int r2 = 0; r2 < 16; r2++)
            s += Tsc[(r2 * 16 + (tid >> 2)) * 4 + (tid & 3)];
        g_Tp[((b * NH + h) * 16 + kb) * 64 + tid] = s;
    }
}

// ---------------------------------------------------------------------------
// Kernel 2: out[q,:] = sum_k (P-1)*V'' + T, P = exp(Q_s K^T) (Q pre-scaled).
// Per tile: plain coalesced copies of the PRE-PACKED fp16 K/V'' tiles
// (half the gmem bytes, zero conversion work), then gemm1 -> exp -> gemm2.
// ---------------------------------------------------------------------------
__global__ void __launch_bounds__(256, 2) k2_attnv(const float* __restrict__ Qg) {
    extern __shared__ u32 smu[];
    u32* Qa = smu;                       // fp16 A-pack : 4096 u32
    u32* Kp = smu + 4096;                // fp16 B-pack : 4224 u32
    u32* Vp = smu + 8320;                // fp16 B-pack : 4224 u32
    float* Tf = (float*)(smu + 12544);   // 64
    // total 12608 u32 = 50432 B -> 2 CTAs/SM

    int tid = threadIdx.x, lane = tid & 31, w = tid >> 5;
    int b = blockIdx.z, h = blockIdx.y, q0 = blockIdx.x << 7;
    int bh = b * NH + h;

    const float* Qb = Qg + ((size_t)b * SEQ + q0) * DIM + h * HD;

    int rb = tid >> 4, c4 = (tid & 15) << 2;
#pragma unroll
    for (int it = 0; it < 8; it++) {
        int r = rb + (it << 4);
        float4 qv = *(const float4*)(Qb + (size_t)r * DIM + c4);
        qv.x *= SCALE; qv.y *= SCALE; qv.z *= SCALE; qv.w *= SCALE;
        stA16f(Qa, r, c4, qv);
    }
    if (tid < 64) {
        float s = 0.f;
        const float* tp = g_Tp + (size_t)bh * 1024 + tid;
#pragma unroll
        for (int kb = 0; kb < 16; kb++) s += tp[kb * 64];
        Tf[tid] = s;
    }

    float o[8][4];
#pragma unroll
    for (int nt = 0; nt < 8; nt++)
#pragma unroll
        for (int t = 0; t < 4; t++) o[nt][t] = 0.f;

    for (int kb = 0; kb < 16; kb++) {
        __syncthreads();   // previous tile fully consumed (also covers Qa/Tf at kb=0)
        const uint4* ks4 = (const uint4*)(g_Kp + ((size_t)(bh * 16 + kb)) * 4224);
        const uint4* vs4 = (const uint4*)(g_Vp + ((size_t)(bh * 16 + kb)) * 4224);
        for (int i = tid; i < 1056; i += 256) {
            ((uint4*)Kp)[i] = ks4[i];
            ((uint4*)Vp)[i] = vs4[i];
        }
        __syncthreads();

#pragma unroll
        for (int half = 0; half < 2; half++) {
            float acc[8][4];
#pragma unroll
            for (int nt = 0; nt < 8; nt++)
#pragma unroll
                for (int tt = 0; tt < 4; tt++) acc[nt][tt] = 0.f;
#pragma unroll
            for (int ks = 0; ks < 4; ks++) {
                uint4 a = ldA16(Qa, ks, w, lane);
#pragma unroll
                for (int nt = 0; nt < 8; nt++) {
                    uint2 bf = ldB16<16>(Kp, ks, half * 8 + nt, lane);
                    mma16f(acc[nt], a, bf);
                }
            }

#pragma unroll
            for (int j2 = 0; j2 < 4; j2++) {
                float e0 = __expf(acc[2 * j2][0]) - 1.0f;
                float e1 = __expf(acc[2 * j2][1]) - 1.0f;
                float e2 = __expf(acc[2 * j2][2]) - 1.0f;
                float e3 = __expf(acc[2 * j2][3]) - 1.0f;
                float e4 = __expf(acc[2 * j2 + 1][0]) - 1.0f;
                float e5 = __expf(acc[2 * j2 + 1][1]) - 1.0f;
                float e6 = __expf(acc[2 * j2 + 1][2]) - 1.0f;
                float e7 = __expf(acc[2 * j2 + 1][3]) - 1.0f;
                uint4 ah;
                ah.x = f16x2_rn(e1, e0);
                ah.y = f16x2_rn(e3, e2);
                ah.z = f16x2_rn(e5, e4);
                ah.w = f16x2_rn(e7, e6);
                int ks2 = half * 4 + j2;
#pragma unroll
                for (int nt = 0; nt < 8; nt++) {
                    uint2 bv = ldB16<8>(Vp, ks2, nt, lane);
                    mma16f(o[nt], ah, bv);
                }
            }
        }
    }

    const float inv1024 = 1.0f / 1024.0f;
    int r = lane >> 2, c2 = (lane & 3) << 1;
    float* obase = g_att + ((size_t)b * SEQ + q0 + 16 * w + r) * DIM + h * HD;
#pragma unroll
    for (int nt = 0; nt < 8; nt++) {
        int d0 = nt * 8 + c2;
        float t0 = Tf[d0], t1 = Tf[d0 + 1];
        *(float2*)(obase + d0) =
            make_float2((o[nt][0] + t0) * inv1024, (o[nt][1] + t1) * inv1024);
        *(float2*)(obase + (size_t)8 * DIM + d0) =
            make_float2((o[nt][2] + t0) * inv1024, (o[nt][3] + t1) * inv1024);
    }
}

// ---------------------------------------------------------------------------
// Kernel 3: out = g_att @ W^T + b.  Single-pass fp16. (r12, proven)
// ---------------------------------------------------------------------------
__global__ void __launch_bounds__(256, 2) k3_linear(const float* __restrict__ Wg,
                                                    const float* __restrict__ bg,
                                                    float* __restrict__ Og) {
    extern __shared__ u32 smu[];
    u32* Xp = smu;             // fp16 A-pack : 4096 u32
    u32* Wp = smu + 4096;      // fp16 B-pack : 4224 u32

    int tid = threadIdx.x, lane = tid & 31, w = tid >> 5;
    int wm = w >> 2, wn = w & 3;
    int n0 = blockIdx.x << 7, m0 = blockIdx.y << 7;

    float acc[4][4][4];
#pragma unroll
    for (int i = 0; i < 4; i++)
#pragma unroll
        for (int j = 0; j < 4; j++)
#pragma unroll
            for (int t = 0; t < 4; t++) acc[i][j][t] = 0.f;

    int rb = tid >> 4, c4 = (tid & 15) << 2;
    for (int d0 = 0; d0 < DIM; d0 += 64) {
        __syncthreads();
#pragma unroll
        for (int it = 0; it < 8; it++) {
            int r = rb + (it << 4);
            stA16f(Xp, r, c4,
                   *(const float4*)(g_att + (size_t)(m0 + r) * DIM + d0 + c4));
            stB16f<16>(Wp, r, c4,
                       *(const float4*)(Wg + (size_t)(n0 + r) * DIM + d0 + c4));
        }
        __syncthreads();

#pragma unroll
        for (int ks = 0; ks < 4; ks++) {
            uint4 ah[4]; uint2 bh[4];
#pragma unroll
            for (int i = 0; i < 4; i++) ah[i] = ldA16(Xp, ks, wm * 4 + i, lane);
#pragma unroll
            for (int j = 0; j < 4; j++) bh[j] = ldB16<16>(Wp, ks, wn * 4 + j, lane);
#pragma unroll
            for (int i = 0; i < 4; i++)
#pragma unroll
                for (int j = 0; j < 4; j++)
                    mma16f(acc[i][j], ah[i], bh[j]);
        }
    }

#pragma unroll
    for (int i = 0; i < 4; i++)
#pragma unroll
        for (int j = 0; j < 4; j++) {
            int r = wm * 64 + i * 16 + (lane >> 2);
            int n = wn * 32 + j * 8 + ((lane & 3) << 1);
            float2 bb = *(const float2*)(bg + n0 + n);
            float* p = Og + (size_t)(m0 + r) * DIM + n0 + n;
            *(float2*)p = make_float2(acc[i][j][0] + bb.x, acc[i][j][1] + bb.y);
            *(float2*)(p + (size_t)8 * DIM) =
                make_float2(acc[i][j][2] + bb.x, acc[i][j][3] + bb.y);
        }
}

// ---------------------------------------------------------------------------

extern "C" void kernel_launch(void* const* d_in, const int* in_sizes, int n_in,
                              void* d_out, int out_size) {
    const float* Q = (const float*)d_in[0];
    const float* K = (const float*)d_in[1];
    const float* V = (const float*)d_in[2];
    const float* W = (const float*)d_in[3];
    const float* bias = (const float*)d_in[4];
    float* out = (float*)d_out;
    (void)in_sizes; (void)n_in; (void)out_size;

    const int smem1 = 12672 * 4;   // 50688
    const int smem2 = 12608 * 4;   // 50432
    const int smem3 = 8320 * 4;    // 33280

    cudaFuncSetAttribute(k1_colsum, cudaFuncAttributeMaxDynamicSharedMemorySize, smem1);
    cudaFuncSetAttribute(k2_attnv,  cudaFuncAttributeMaxDynamicSharedMemorySize, smem2);
    cudaFuncSetAttribute(k3_linear, cudaFuncAttributeMaxDynamicSharedMemorySize, smem3);

    dim3 gAttn(SEQ / 128, NH, NB);          // 1024 CTAs
    k1_colsum<<<gAttn, 256, smem1>>>(Q, K, V);
    k2_attnv<<<gAttn, 256, smem2>>>(Q);

    dim3 gLin(DIM / 128, (NB * SEQ) / 128); // 512 CTAs
    k3_linear<<<gLin, 256, smem3>>>(W, bias, out);
}

// round 16
// speedup vs baseline: 1.0697x; 1.0156x over previous
#include <cuda_runtime.h>

#define NB 4
#define NH 16
#define SEQ 2048
#define DIM 1024
#define HD 64
#define SCALE 0.03125f   // 1/sqrt(1024)

typedef unsigned int u32;

// Scratch (allocation-free rule: __device__ globals)
__device__ float g_att[(size_t)NB * SEQ * DIM];
__device__ u32 g_Kp[(size_t)NB * NH * 16 * 4224];   // fp16 K B-packs (per b,h,kblock)
__device__ u32 g_Vp[(size_t)NB * NH * 16 * 4224];   // fp16 V'' B-packs
__device__ float g_Tp[NB * NH * 16 * 64];           // per-kblock partial T

// ---------------------------------------------------------------------------
// Low-level helpers (portable sm_80+ PTX)
// ---------------------------------------------------------------------------
__device__ __forceinline__ u32 bf16x2_rn(float hi, float lo) {
    u32 r; asm("cvt.rn.bf16x2.f32 %0, %1, %2;" : "=r"(r) : "f"(hi), "f"(lo)); return r;
}
__device__ __forceinline__ u32 f16x2_rn(float hi, float lo) {
    u32 r; asm("cvt.rn.f16x2.f32 %0, %1, %2;" : "=r"(r) : "f"(hi), "f"(lo)); return r;
}
__device__ __forceinline__ u32 ex2h2(u32 x) {     // 2 exps per MUFU op
    u32 r; asm("ex2.approx.f16x2 %0, %1;" : "=r"(r) : "r"(x)); return r;
}
__device__ __forceinline__ u32 hsubx2(u32 a, u32 b) {
    u32 r; asm("sub.f16x2 %0, %1, %2;" : "=r"(r) : "r"(a), "r"(b)); return r;
}
__device__ __forceinline__ float2 h2f2(u32 e) {
    float2 f;
    asm("{.reg .b16 h0,h1; mov.b32 {h0,h1}, %2; cvt.f32.f16 %0, h0; cvt.f32.f16 %1, h1;}"
        : "=f"(f.x), "=f"(f.y) : "r"(e));
    return f;
}

// m16n8k16 bf16 mma
__device__ __forceinline__ void mma16(float c[4], uint4 a, uint2 b) {
    asm volatile(
        "mma.sync.aligned.m16n8k16.row.col.f32.bf16.bf16.f32 "
        "{%0,%1,%2,%3}, {%4,%5,%6,%7}, {%8,%9}, {%0,%1,%2,%3};"
        : "+f"(c[0]), "+f"(c[1]), "+f"(c[2]), "+f"(c[3])
        : "r"(a.x), "r"(a.y), "r"(a.z), "r"(a.w), "r"(b.x), "r"(b.y));
}
// m16n8k16 fp16 mma
__device__ __forceinline__ void mma16f(float c[4], uint4 a, uint2 b) {
    asm volatile(
        "mma.sync.aligned.m16n8k16.row.col.f32.f16.f16.f32 "
        "{%0,%1,%2,%3}, {%4,%5,%6,%7}, {%8,%9}, {%0,%1,%2,%3};"
        : "+f"(c[0]), "+f"(c[1]), "+f"(c[2]), "+f"(c[3])
        : "r"(a.x), "r"(a.y), "r"(a.z), "r"(a.w), "r"(b.x), "r"(b.y));
}

// ---------------------------------------------------------------------------
// 16-bit fragment packs (m16n8k16). A-pack: [ks][mt(8)][lane] uint4.
// B-pack padded: [ks][nt][33 lane-pairs] uint2.
// ---------------------------------------------------------------------------
__device__ __forceinline__ uint4 ldA16(const u32* A, int ks, int mt, int lane) {
    return *(const uint4*)(A + ((size_t)((ks * 8 + mt) * 32 + lane)) * 4);
}
template<int NT>
__device__ __forceinline__ uint2 ldB16(const u32* B, int ks, int nt, int lane) {
    return *(const uint2*)(B + ((size_t)((ks * NT + nt) * 33 + lane)) * 2);
}
// bf16 stores (k1)
__device__ __forceinline__ void stA16_rn(u32* A, int r, int c4, float4 v) {
    int ks = c4 >> 4, kkb = c4 & 15;
    const float* f = &v.x;
#pragma unroll
    for (int p = 0; p < 2; p++) {
        int kk = kkb + 2 * p;
        int c = (kk & 7) >> 1, slot = ((r >> 3) & 1) | ((kk >> 3) << 1);
        int idx = ((ks * 8 + (r >> 4)) * 32 + ((r & 7) << 2) + c) * 4 + slot;
        A[idx] = bf16x2_rn(f[2 * p + 1], f[2 * p]);
    }
}
template<int NT>
__device__ __forceinline__ void stB16_rn(u32* B, int n, int c4, float4 v) {
    int ks = c4 >> 4, kkb = c4 & 15;
    const float* f = &v.x;
#pragma unroll
    for (int p = 0; p < 2; p++) {
        int kk = kkb + 2 * p;
        int c = (kk & 7) >> 1, breg = kk >> 3;
        int idx = ((ks * NT + (n >> 3)) * 33 + ((n & 7) << 2) + c) * 2 + breg;
        B[idx] = bf16x2_rn(f[2 * p + 1], f[2 * p]);
    }
}
// fp16 stores
__device__ __forceinline__ void stA16f(u32* A, int r, int c4, float4 v) {
    int ks = c4 >> 4, kkb = c4 & 15;
    const float* f = &v.x;
#pragma unroll
    for (int p = 0; p < 2; p++) {
        int kk = kkb + 2 * p;
        int c = (kk & 7) >> 1, slot = ((r >> 3) & 1) | ((kk >> 3) << 1);
        int idx = ((ks * 8 + (r >> 4)) * 32 + ((r & 7) << 2) + c) * 4 + slot;
        A[idx] = f16x2_rn(f[2 * p + 1], f[2 * p]);
    }
}
template<int NT>
__device__ __forceinline__ void stB16f(u32* B, int n, int c4, float4 v) {
    int ks = c4 >> 4, kkb = c4 & 15;
    const float* f = &v.x;
#pragma unroll
    for (int p = 0; p < 2; p++) {
        int kk = kkb + 2 * p;
        int c = (kk & 7) >> 1, breg = kk >> 3;
        int idx = ((ks * NT + (n >> 3)) * 33 + ((n & 7) << 2) + c) * 2 + breg;
        B[idx] = f16x2_rn(f[2 * p + 1], f[2 * p]);
    }
}

// ---------------------------------------------------------------------------
// Kernel 1: per (b,h,kblock):
//   (a) write fp16 K B-pack to g_Kp (for k2)
//   (b) colsum l[k] = sum_q exp(s[q,k])  (bf16 mma + packed fp16 ex2)
//   (c) V'' = 1024*V/colsum -> fp16 B-pack to g_Vp; partial T to g_Tp
// (r15, proven)
// ---------------------------------------------------------------------------
__global__ void __launch_bounds__(256) k1_colsum(const float* __restrict__ Qg,
                                                 const float* __restrict__ Kg,
                                                 const float* __restrict__ Vg) {
    extern __shared__ u32 smu[];
    u32* Ka = smu;                        // 4096 u32
    u32* Qb = smu + 4096;                 // 4224 u32
    float* colsum = (float*)(smu + 8320); // 128
    u32* Po = smu + 8448;                 // 4224 (K-pack out, then V-pack out)

    int tid = threadIdx.x, lane = tid & 31, w = tid >> 5;
    int wm = w >> 2, wn = w & 3;
    int b = blockIdx.z, h = blockIdx.y, kb = blockIdx.x, k0 = kb << 7;

    const float* Kb = Kg + ((size_t)b * SEQ + k0) * DIM + h * HD;
    const float* Qbase = Qg + (size_t)b * SEQ * DIM + h * HD;
    const float* Vb = Vg + ((size_t)b * SEQ + k0) * DIM + h * HD;
    const size_t pbase = ((size_t)((b * NH + h) * 16 + kb)) * 4224;

    const float C2 = SCALE * 1.4426950408889634f;   // SCALE * log2(e)

    int rb = tid >> 4, c4 = (tid & 15) << 2;
#pragma unroll
    for (int it = 0; it < 8; it++) {
        int r = rb + (it << 4);
        float4 kv = *(const float4*)(Kb + (size_t)r * DIM + c4);
        stA16_rn(Ka, r, c4, kv);        // bf16 A-pack for own mma
        stB16f<16>(Po, r, c4, kv);      // fp16 B-pack for k2
    }
    if (tid < 128) colsum[tid] = 0.f;
    __syncthreads();
    for (int i = tid; i < 1056; i += 256)
        ((uint4*)(g_Kp + pbase))[i] = ((const uint4*)Po)[i];

    float sume[4][2];
#pragma unroll
    for (int i = 0; i < 4; i++) { sume[i][0] = 0.f; sume[i][1] = 0.f; }

    for (int q0 = 0; q0 < SEQ; q0 += 128) {
        __syncthreads();
#pragma unroll
        for (int it = 0; it < 8; it++) {
            int n = rb + (it << 4);
            stB16_rn<16>(Qb, n, c4,
                         *(const float4*)(Qbase + (size_t)(q0 + n) * DIM + c4));
        }
        __syncthreads();

        float acc[4][4][4];
#pragma unroll
        for (int i = 0; i < 4; i++)
#pragma unroll
            for (int j = 0; j < 4; j++)
#pragma unroll
                for (int t = 0; t < 4; t++) acc[i][j][t] = 0.f;

#pragma unroll
        for (int ks = 0; ks < 4; ks++) {
            uint4 af[4]; uint2 bf[4];
#pragma unroll
            for (int i = 0; i < 4; i++) af[i] = ldA16(Ka, ks, wm * 4 + i, lane);
#pragma unroll
            for (int j = 0; j < 4; j++) bf[j] = ldB16<16>(Qb, ks, wn * 4 + j, lane);
#pragma unroll
            for (int i = 0; i < 4; i++)
#pragma unroll
                for (int j = 0; j < 4; j++) mma16(acc[i][j], af[i], bf[j]);
        }
#pragma unroll
        for (int i = 0; i < 4; i++)
#pragma unroll
            for (int j = 0; j < 4; j++) {
                u32 e01 = ex2h2(f16x2_rn(acc[i][j][1] * C2, acc[i][j][0] * C2));
                u32 e23 = ex2h2(f16x2_rn(acc[i][j][3] * C2, acc[i][j][2] * C2));
                float2 f01 = h2f2(e01);
                float2 f23 = h2f2(e23);
                sume[i][0] += f01.x + f01.y;
                sume[i][1] += f23.x + f23.y;
            }
    }

#pragma unroll
    for (int i = 0; i < 4; i++)
#pragma unroll
        for (int hh = 0; hh < 2; hh++) {
            float v = sume[i][hh];
            v += __shfl_xor_sync(0xffffffffu, v, 1);
            v += __shfl_xor_sync(0xffffffffu, v, 2);
            if ((lane & 3) == 0)
                atomicAdd(&colsum[wm * 64 + i * 16 + (lane >> 2) + hh * 8], v);
        }
    __syncthreads();

    // ---- V phase: V'' = 1024*V/colsum -> fp16 B-pack (NT=8) + partial T ----
    float Tl[4] = {0.f, 0.f, 0.f, 0.f};
#pragma unroll
    for (int it = 0; it < 8; it++) {
        int kt = rb + (it << 4);
        float rl = 1024.0f / colsum[kt];
        float4 v = *(const float4*)(Vb + (size_t)kt * DIM + c4);
        v.x *= rl; v.y *= rl; v.z *= rl; v.w *= rl;
        Tl[0] += v.x; Tl[1] += v.y; Tl[2] += v.z; Tl[3] += v.w;
        float4 oth;
        oth.x = __shfl_xor_sync(0xffffffffu, v.x, 16);
        oth.y = __shfl_xor_sync(0xffffffffu, v.y, 16);
        oth.z = __shfl_xor_sync(0xffffffffu, v.z, 16);
        oth.w = __shfl_xor_sync(0xffffffffu, v.w, 16);
        float4 ve, vo;
        if (lane & 16) { ve = oth; vo = v; } else { ve = v; vo = oth; }
        if (((lane >> 4) & 1) == (it & 1)) {
            int ke = kt & ~1;
            int ksv = ke >> 4, kk = ke & 15;
            int c = (kk & 7) >> 1, breg = kk >> 3;
            const float* pe = &ve.x; const float* po = &vo.x;
#pragma unroll
            for (int j = 0; j < 4; j++) {
                int d = c4 + j;
                int idx = ((ksv * 8 + (d >> 3)) * 33 + ((d & 7) << 2) + c) * 2 + breg;
                Po[idx] = f16x2_rn(po[j], pe[j]);
            }
        }
    }
    float* Tsc = (float*)Qb;
#pragma unroll
    for (int j = 0; j < 4; j++) Tsc[tid * 4 + j] = Tl[j];
    __syncthreads();
    for (int i = tid; i < 1056; i += 256)
        ((uint4*)(g_Vp + pbase))[i] = ((const uint4*)Po)[i];
    if (tid < 64) {
        float s = 0.f;
#pragma unroll
        for (int r2 = 0; r2 < 16; r2++)
            s += Tsc[(r2 * 16 + (tid >> 2)) * 4 + (tid & 3)];
        g_Tp[((b * NH + h) * 16 + kb) * 64 + tid] = s;
    }
}

// ---------------------------------------------------------------------------
// Kernel 2: out[q,:] = sum_k (P-1)*V'' + T.  Q pre-scaled by SCALE*log2(e)
// so acc is directly the ex2 argument; P-1 computed with packed fp16
// ex2.approx + sub (half the MUFU, half the epilogue issue ops).
// ---------------------------------------------------------------------------
__global__ void __launch_bounds__(256, 2) k2_attnv(const float* __restrict__ Qg) {
    extern __shared__ u32 smu[];
    u32* Qa = smu;                       // fp16 A-pack : 4096 u32
    u32* Kp = smu + 4096;                // fp16 B-pack : 4224 u32
    u32* Vp = smu + 8320;                // fp16 B-pack : 4224 u32
    float* Tf = (float*)(smu + 12544);   // 64

    int tid = threadIdx.x, lane = tid & 31, w = tid >> 5;
    int b = blockIdx.z, h = blockIdx.y, q0 = blockIdx.x << 7;
    int bh = b * NH + h;

    const float* Qb = Qg + ((size_t)b * SEQ + q0) * DIM + h * HD;
    const float C2 = SCALE * 1.4426950408889634f;   // SCALE * log2(e)
    const u32 ONES2 = 0x3C003C00u;                  // (1.0h, 1.0h)

    int rb = tid >> 4, c4 = (tid & 15) << 2;
#pragma unroll
    for (int it = 0; it < 8; it++) {
        int r = rb + (it << 4);
        float4 qv = *(const float4*)(Qb + (size_t)r * DIM + c4);
        qv.x *= C2; qv.y *= C2; qv.z *= C2; qv.w *= C2;
        stA16f(Qa, r, c4, qv);
    }
    if (tid < 64) {
        float s = 0.f;
        const float* tp = g_Tp + (size_t)bh * 1024 + tid;
#pragma unroll
        for (int kb = 0; kb < 16; kb++) s += tp[kb * 64];
        Tf[tid] = s;
    }

    float o[8][4];
#pragma unroll
    for (int nt = 0; nt < 8; nt++)
#pragma unroll
        for (int t = 0; t < 4; t++) o[nt][t] = 0.f;

    for (int kb = 0; kb < 16; kb++) {
        __syncthreads();
        const uint4* ks4 = (const uint4*)(g_Kp + ((size_t)(bh * 16 + kb)) * 4224);
        const uint4* vs4 = (const uint4*)(g_Vp + ((size_t)(bh * 16 + kb)) * 4224);
        for (int i = tid; i < 1056; i += 256) {
            ((uint4*)Kp)[i] = ks4[i];
            ((uint4*)Vp)[i] = vs4[i];
        }
        __syncthreads();

#pragma unroll
        for (int half = 0; half < 2; half++) {
            float acc[8][4];
#pragma unroll
            for (int nt = 0; nt < 8; nt++)
#pragma unroll
                for (int tt = 0; tt < 4; tt++) acc[nt][tt] = 0.f;
#pragma unroll
            for (int ks = 0; ks < 4; ks++) {
                uint4 a = ldA16(Qa, ks, w, lane);
#pragma unroll
                for (int nt = 0; nt < 8; nt++) {
                    uint2 bf = ldB16<16>(Kp, ks, half * 8 + nt, lane);
                    mma16f(acc[nt], a, bf);
                }
            }

#pragma unroll
            for (int j2 = 0; j2 < 4; j2++) {
                // P-1 via packed fp16 ex2: A-frag built in 12 packed ops
                uint4 ah;
                ah.x = hsubx2(ex2h2(f16x2_rn(acc[2 * j2][1], acc[2 * j2][0])), ONES2);
                ah.y = hsubx2(ex2h2(f16x2_rn(acc[2 * j2][3], acc[2 * j2][2])), ONES2);
                ah.z = hsubx2(ex2h2(f16x2_rn(acc[2 * j2 + 1][1], acc[2 * j2 + 1][0])), ONES2);
                ah.w = hsubx2(ex2h2(f16x2_rn(acc[2 * j2 + 1][3], acc[2 * j2 + 1][2])), ONES2);
                int ks2 = half * 4 + j2;
#pragma unroll
                for (int nt = 0; nt < 8; nt++) {
                    uint2 bv = ldB16<8>(Vp, ks2, nt, lane);
                    mma16f(o[nt], ah, bv);
                }
            }
        }
    }

    const float inv1024 = 1.0f / 1024.0f;
    int r = lane >> 2, c2 = (lane & 3) << 1;
    float* obase = g_att + ((size_t)b * SEQ + q0 + 16 * w + r) * DIM + h * HD;
#pragma unroll
    for (int nt = 0; nt < 8; nt++) {
        int d0 = nt * 8 + c2;
        float t0 = Tf[d0], t1 = Tf[d0 + 1];
        *(float2*)(obase + d0) =
            make_float2((o[nt][0] + t0) * inv1024, (o[nt][1] + t1) * inv1024);
        *(float2*)(obase + (size_t)8 * DIM + d0) =
            make_float2((o[nt][2] + t0) * inv1024, (o[nt][3] + t1) * inv1024);
    }
}

// ---------------------------------------------------------------------------
// Kernel 3: out = g_att @ W^T + b.  Single-pass fp16. (r12, proven)
// ---------------------------------------------------------------------------
__global__ void __launch_bounds__(256, 2) k3_linear(const float* __restrict__ Wg,
                                                    const float* __restrict__ bg,
                                                    float* __restrict__ Og) {
    extern __shared__ u32 smu[];
    u32* Xp = smu;             // fp16 A-pack : 4096 u32
    u32* Wp = smu + 4096;      // fp16 B-pack : 4224 u32

    int tid = threadIdx.x, lane = tid & 31, w = tid >> 5;
    int wm = w >> 2, wn = w & 3;
    int n0 = blockIdx.x << 7, m0 = blockIdx.y << 7;

    float acc[4][4][4];
#pragma unroll
    for (int i = 0; i < 4; i++)
#pragma unroll
        for (int j = 0; j < 4; j++)
#pragma unroll
            for (int t = 0; t < 4; t++) acc[i][j][t] = 0.f;

    int rb = tid >> 4, c4 = (tid & 15) << 2;
    for (int d0 = 0; d0 < DIM; d0 += 64) {
        __syncthreads();
#pragma unroll
        for (int it = 0; it < 8; it++) {
            int r = rb + (it << 4);
            stA16f(Xp, r, c4,
                   *(const float4*)(g_att + (size_t)(m0 + r) * DIM + d0 + c4));
            stB16f<16>(Wp, r, c4,
                       *(const float4*)(Wg + (size_t)(n0 + r) * DIM + d0 + c4));
        }
        __syncthreads();

#pragma unroll
        for (int ks = 0; ks < 4; ks++) {
            uint4 ah[4]; uint2 bh[4];
#pragma unroll
            for (int i = 0; i < 4; i++) ah[i] = ldA16(Xp, ks, wm * 4 + i, lane);
#pragma unroll
            for (int j = 0; j < 4; j++) bh[j] = ldB16<16>(Wp, ks, wn * 4 + j, lane);
#pragma unroll
            for (int i = 0; i < 4; i++)
#pragma unroll
                for (int j = 0; j < 4; j++)
                    mma16f(acc[i][j], ah[i], bh[j]);
        }
    }

#pragma unroll
    for (int i = 0; i < 4; i++)
#pragma unroll
        for (int j = 0; j < 4; j++) {
            int r = wm * 64 + i * 16 + (lane >> 2);
            int n = wn * 32 + j * 8 + ((lane & 3) << 1);
            float2 bb = *(const float2*)(bg + n0 + n);
            float* p = Og + (size_t)(m0 + r) * DIM + n0 + n;
            *(float2*)p = make_float2(acc[i][j][0] + bb.x, acc[i][j][1] + bb.y);
            *(float2*)(p + (size_t)8 * DIM) =
                make_float2(acc[i][j][2] + bb.x, acc[i][j][3] + bb.y);
        }
}

// ---------------------------------------------------------------------------

extern "C" void kernel_launch(void* const* d_in, const int* in_sizes, int n_in,
                              void* d_out, int out_size) {
    const float* Q = (const float*)d_in[0];
    const float* K = (const float*)d_in[1];
    const float* V = (const float*)d_in[2];
    const float* W = (const float*)d_in[3];
    const float* bias = (const float*)d_in[4];
    float* out = (float*)d_out;
    (void)in_sizes; (void)n_in; (void)out_size;

    const int smem1 = 12672 * 4;   // 50688
    const int smem2 = 12608 * 4;   // 50432
    const int smem3 = 8320 * 4;    // 33280

    cudaFuncSetAttribute(k1_colsum, cudaFuncAttributeMaxDynamicSharedMemorySize, smem1);
    cudaFuncSetAttribute(k2_attnv,  cudaFuncAttributeMaxDynamicSharedMemorySize, smem2);
    cudaFuncSetAttribute(k3_linear, cudaFuncAttributeMaxDynamicSharedMemorySize, smem3);

    dim3 gAttn(SEQ / 128, NH, NB);          // 1024 CTAs
    k1_colsum<<<gAttn, 256, smem1>>>(Q, K, V);
    k2_attnv<<<gAttn, 256, smem2>>>(Q);

    dim3 gLin(DIM / 128, (NB * SEQ) / 128); // 512 CTAs
    k3_linear<<<gLin, 256, smem3>>>(W, bias, out);
}

// round 17
// speedup vs baseline: 1.1798x; 1.1030x over previous
#include <cuda_runtime.h>

#define NB 4
#define NH 16
#define SEQ 2048
#define DIM 1024
#define HD 64
#define SCALE 0.03125f   // 1/sqrt(1024)

typedef unsigned int u32;

// Scratch (allocation-free rule: __device__ globals)
__device__ float g_att[(size_t)NB * SEQ * DIM];
__device__ u32 g_Kp[(size_t)NB * NH * 16 * 4224];   // fp16 K B-packs (per b,h,kblock)
__device__ u32 g_Vp[(size_t)NB * NH * 16 * 4224];   // fp16 V'' B-packs
__device__ float g_Tp[NB * NH * 16 * 64];           // per-kblock partial T

// ---------------------------------------------------------------------------
// Low-level helpers (portable sm_80+ PTX)
// ---------------------------------------------------------------------------
__device__ __forceinline__ u32 smem_u32(const void* p) {
    u32 a;
    asm("{ .reg .u64 t; cvta.to.shared.u64 t, %1; cvt.u32.u64 %0, t; }"
        : "=r"(a) : "l"(p));
    return a;
}
__device__ __forceinline__ void cpa16(u32 saddr, const void* g) {
    asm volatile("cp.async.ca.shared.global [%0], [%1], 16;" :: "r"(saddr), "l"(g));
}
#define CP_COMMIT() asm volatile("cp.async.commit_group;" ::: "memory")
#define CP_WAIT0()  asm volatile("cp.async.wait_group 0;" ::: "memory")

__device__ __forceinline__ u32 bf16x2_rn(float hi, float lo) {
    u32 r; asm("cvt.rn.bf16x2.f32 %0, %1, %2;" : "=r"(r) : "f"(hi), "f"(lo)); return r;
}
__device__ __forceinline__ u32 f16x2_rn(float hi, float lo) {
    u32 r; asm("cvt.rn.f16x2.f32 %0, %1, %2;" : "=r"(r) : "f"(hi), "f"(lo)); return r;
}
__device__ __forceinline__ u32 ex2h2(u32 x) {     // 2 exps per MUFU op
    u32 r; asm("ex2.approx.f16x2 %0, %1;" : "=r"(r) : "r"(x)); return r;
}
__device__ __forceinline__ u32 hsubx2(u32 a, u32 b) {
    u32 r; asm("sub.f16x2 %0, %1, %2;" : "=r"(r) : "r"(a), "r"(b)); return r;
}
__device__ __forceinline__ float2 h2f2(u32 e) {
    float2 f;
    asm("{.reg .b16 h0,h1; mov.b32 {h0,h1}, %2; cvt.f32.f16 %0, h0; cvt.f32.f16 %1, h1;}"
        : "=f"(f.x), "=f"(f.y) : "r"(e));
    return f;
}

// m16n8k16 bf16 mma
__device__ __forceinline__ void mma16(float c[4], uint4 a, uint2 b) {
    asm volatile(
        "mma.sync.aligned.m16n8k16.row.col.f32.bf16.bf16.f32 "
        "{%0,%1,%2,%3}, {%4,%5,%6,%7}, {%8,%9}, {%0,%1,%2,%3};"
        : "+f"(c[0]), "+f"(c[1]), "+f"(c[2]), "+f"(c[3])
        : "r"(a.x), "r"(a.y), "r"(a.z), "r"(a.w), "r"(b.x), "r"(b.y));
}
// m16n8k16 fp16 mma
__device__ __forceinline__ void mma16f(float c[4], uint4 a, uint2 b) {
    asm volatile(
        "mma.sync.aligned.m16n8k16.row.col.f32.f16.f16.f32 "
        "{%0,%1,%2,%3}, {%4,%5,%6,%7}, {%8,%9}, {%0,%1,%2,%3};"
        : "+f"(c[0]), "+f"(c[1]), "+f"(c[2]), "+f"(c[3])
        : "r"(a.x), "r"(a.y), "r"(a.z), "r"(a.w), "r"(b.x), "r"(b.y));
}

// ---------------------------------------------------------------------------
// 16-bit fragment packs (m16n8k16). A-pack: [ks][mt(8)][lane] uint4.
// B-pack padded: [ks][nt][33 lane-pairs] uint2.
// ---------------------------------------------------------------------------
__device__ __forceinline__ uint4 ldA16(const u32* A, int ks, int mt, int lane) {
    return *(const uint4*)(A + ((size_t)((ks * 8 + mt) * 32 + lane)) * 4);
}
template<int NT>
__device__ __forceinline__ uint2 ldB16(const u32* B, int ks, int nt, int lane) {
    return *(const uint2*)(B + ((size_t)((ks * NT + nt) * 33 + lane)) * 2);
}
// bf16 stores (k1)
__device__ __forceinline__ void stA16_rn(u32* A, int r, int c4, float4 v) {
    int ks = c4 >> 4, kkb = c4 & 15;
    const float* f = &v.x;
#pragma unroll
    for (int p = 0; p < 2; p++) {
        int kk = kkb + 2 * p;
        int c = (kk & 7) >> 1, slot = ((r >> 3) & 1) | ((kk >> 3) << 1);
        int idx = ((ks * 8 + (r >> 4)) * 32 + ((r & 7) << 2) + c) * 4 + slot;
        A[idx] = bf16x2_rn(f[2 * p + 1], f[2 * p]);
    }
}
template<int NT>
__device__ __forceinline__ void stB16_rn(u32* B, int n, int c4, float4 v) {
    int ks = c4 >> 4, kkb = c4 & 15;
    const float* f = &v.x;
#pragma unroll
    for (int p = 0; p < 2; p++) {
        int kk = kkb + 2 * p;
        int c = (kk & 7) >> 1, breg = kk >> 3;
        int idx = ((ks * NT + (n >> 3)) * 33 + ((n & 7) << 2) + c) * 2 + breg;
        B[idx] = bf16x2_rn(f[2 * p + 1], f[2 * p]);
    }
}
// fp16 stores
__device__ __forceinline__ void stA16f(u32* A, int r, int c4, float4 v) {
    int ks = c4 >> 4, kkb = c4 & 15;
    const float* f = &v.x;
#pragma unroll
    for (int p = 0; p < 2; p++) {
        int kk = kkb + 2 * p;
        int c = (kk & 7) >> 1, slot = ((r >> 3) & 1) | ((kk >> 3) << 1);
        int idx = ((ks * 8 + (r >> 4)) * 32 + ((r & 7) << 2) + c) * 4 + slot;
        A[idx] = f16x2_rn(f[2 * p + 1], f[2 * p]);
    }
}
template<int NT>
__device__ __forceinline__ void stB16f(u32* B, int n, int c4, float4 v) {
    int ks = c4 >> 4, kkb = c4 & 15;
    const float* f = &v.x;
#pragma unroll
    for (int p = 0; p < 2; p++) {
        int kk = kkb + 2 * p;
        int c = (kk & 7) >> 1, breg = kk >> 3;
        int idx = ((ks * NT + (n >> 3)) * 33 + ((n & 7) << 2) + c) * 2 + breg;
        B[idx] = f16x2_rn(f[2 * p + 1], f[2 * p]);
    }
}

// ---------------------------------------------------------------------------
// Kernel 1: per (b,h,kblock):
//   (a) write fp16 K B-pack to g_Kp (for k2)
//   (b) colsum l[k] = sum_q exp(s[q,k])  (bf16 mma + packed fp16 ex2)
//   (c) V'' = 1024*V/colsum -> fp16 B-pack to g_Vp; partial T to g_Tp
// (r15, proven)
// ---------------------------------------------------------------------------
__global__ void __launch_bounds__(256) k1_colsum(const float* __restrict__ Qg,
                                                 const float* __restrict__ Kg,
                                                 const float* __restrict__ Vg) {
    extern __shared__ u32 smu[];
    u32* Ka = smu;                        // 4096 u32
    u32* Qb = smu + 4096;                 // 4224 u32
    float* colsum = (float*)(smu + 8320); // 128
    u32* Po = smu + 8448;                 // 4224 (K-pack out, then V-pack out)

    int tid = threadIdx.x, lane = tid & 31, w = tid >> 5;
    int wm = w >> 2, wn = w & 3;
    int b = blockIdx.z, h = blockIdx.y, kb = blockIdx.x, k0 = kb << 7;

    const float* Kb = Kg + ((size_t)b * SEQ + k0) * DIM + h * HD;
    const float* Qbase = Qg + (size_t)b * SEQ * DIM + h * HD;
    const float* Vb = Vg + ((size_t)b * SEQ + k0) * DIM + h * HD;
    const size_t pbase = ((size_t)((b * NH + h) * 16 + kb)) * 4224;

    const float C2 = SCALE * 1.4426950408889634f;   // SCALE * log2(e)

    int rb = tid >> 4, c4 = (tid & 15) << 2;
#pragma unroll
    for (int it = 0; it < 8; it++) {
        int r = rb + (it << 4);
        float4 kv = *(const float4*)(Kb + (size_t)r * DIM + c4);
        stA16_rn(Ka, r, c4, kv);        // bf16 A-pack for own mma
        stB16f<16>(Po, r, c4, kv);      // fp16 B-pack for k2
    }
    if (tid < 128) colsum[tid] = 0.f;
    __syncthreads();
    for (int i = tid; i < 1056; i += 256)
        ((uint4*)(g_Kp + pbase))[i] = ((const uint4*)Po)[i];

    float sume[4][2];
#pragma unroll
    for (int i = 0; i < 4; i++) { sume[i][0] = 0.f; sume[i][1] = 0.f; }

    for (int q0 = 0; q0 < SEQ; q0 += 128) {
        __syncthreads();
#pragma unroll
        for (int it = 0; it < 8; it++) {
            int n = rb + (it << 4);
            stB16_rn<16>(Qb, n, c4,
                         *(const float4*)(Qbase + (size_t)(q0 + n) * DIM + c4));
        }
        __syncthreads();

        float acc[4][4][4];
#pragma unroll
        for (int i = 0; i < 4; i++)
#pragma unroll
            for (int j = 0; j < 4; j++)
#pragma unroll
                for (int t = 0; t < 4; t++) acc[i][j][t] = 0.f;

#pragma unroll
        for (int ks = 0; ks < 4; ks++) {
            uint4 af[4]; uint2 bf[4];
#pragma unroll
            for (int i = 0; i < 4; i++) af[i] = ldA16(Ka, ks, wm * 4 + i, lane);
#pragma unroll
            for (int j = 0; j < 4; j++) bf[j] = ldB16<16>(Qb, ks, wn * 4 + j, lane);
#pragma unroll
            for (int i = 0; i < 4; i++)
#pragma unroll
                for (int j = 0; j < 4; j++) mma16(acc[i][j], af[i], bf[j]);
        }
#pragma unroll
        for (int i = 0; i < 4; i++)
#pragma unroll
            for (int j = 0; j < 4; j++) {
                u32 e01 = ex2h2(f16x2_rn(acc[i][j][1] * C2, acc[i][j][0] * C2));
                u32 e23 = ex2h2(f16x2_rn(acc[i][j][3] * C2, acc[i][j][2] * C2));
                float2 f01 = h2f2(e01);
                float2 f23 = h2f2(e23);
                sume[i][0] += f01.x + f01.y;
                sume[i][1] += f23.x + f23.y;
            }
    }

#pragma unroll
    for (int i = 0; i < 4; i++)
#pragma unroll
        for (int hh = 0; hh < 2; hh++) {
            float v = sume[i][hh];
            v += __shfl_xor_sync(0xffffffffu, v, 1);
            v += __shfl_xor_sync(0xffffffffu, v, 2);
            if ((lane & 3) == 0)
                atomicAdd(&colsum[wm * 64 + i * 16 + (lane >> 2) + hh * 8], v);
        }
    __syncthreads();

    // ---- V phase: V'' = 1024*V/colsum -> fp16 B-pack (NT=8) + partial T ----
    float Tl[4] = {0.f, 0.f, 0.f, 0.f};
#pragma unroll
    for (int it = 0; it < 8; it++) {
        int kt = rb + (it << 4);
        float rl = 1024.0f / colsum[kt];
        float4 v = *(const float4*)(Vb + (size_t)kt * DIM + c4);
        v.x *= rl; v.y *= rl; v.z *= rl; v.w *= rl;
        Tl[0] += v.x; Tl[1] += v.y; Tl[2] += v.z; Tl[3] += v.w;
        float4 oth;
        oth.x = __shfl_xor_sync(0xffffffffu, v.x, 16);
        oth.y = __shfl_xor_sync(0xffffffffu, v.y, 16);
        oth.z = __shfl_xor_sync(0xffffffffu, v.z, 16);
        oth.w = __shfl_xor_sync(0xffffffffu, v.w, 16);
        float4 ve, vo;
        if (lane & 16) { ve = oth; vo = v; } else { ve = v; vo = oth; }
        if (((lane >> 4) & 1) == (it & 1)) {
            int ke = kt & ~1;
            int ksv = ke >> 4, kk = ke & 15;
            int c = (kk & 7) >> 1, breg = kk >> 3;
            const float* pe = &ve.x; const float* po = &vo.x;
#pragma unroll
            for (int j = 0; j < 4; j++) {
                int d = c4 + j;
                int idx = ((ksv * 8 + (d >> 3)) * 33 + ((d & 7) << 2) + c) * 2 + breg;
                Po[idx] = f16x2_rn(po[j], pe[j]);
            }
        }
    }
    float* Tsc = (float*)Qb;
#pragma unroll
    for (int j = 0; j < 4; j++) Tsc[tid * 4 + j] = Tl[j];
    __syncthreads();
    for (int i = tid; i < 1056; i += 256)
        ((uint4*)(g_Vp + pbase))[i] = ((const uint4*)Po)[i];
    if (tid < 64) {
        float s = 0.f;
#pragma unroll
        for (int r2 = 0; r2 < 16; r2++)
            s += Tsc[(r2 * 16 + (tid >> 2)) * 4 + (tid & 3)];
        g_Tp[((b * NH + h) * 16 + kb) * 64 + tid] = s;
    }
}

// ---------------------------------------------------------------------------
// Kernel 2: out[q,:] = sum_k (P-1)*V'' + T.
// Double-buffered cp.async streaming of the pre-packed fp16 K/V'' tiles:
// tile t+1 lands while tile t computes. One sync per tile, no register cost.
// ---------------------------------------------------------------------------
__global__ void __launch_bounds__(256, 2) k2_attnv(const float* __restrict__ Qg) {
    extern __shared__ u32 smu[];
    u32* Qa = smu;                        // fp16 A-pack : 4096
    u32* KpB[2] = { smu + 4096,  smu + 8320 };    // 4224 each
    u32* VpB[2] = { smu + 12544, smu + 16768 };   // 4224 each
    float* Tf = (float*)(smu + 20992);    // 64
    // total 21056 u32 = 84224 B -> 2 CTAs/SM (168 KB)

    int tid = threadIdx.x, lane = tid & 31, w = tid >> 5;
    int b = blockIdx.z, h = blockIdx.y, q0 = blockIdx.x << 7;
    int bh = b * NH + h;

    const float* Qb = Qg + ((size_t)b * SEQ + q0) * DIM + h * HD;
    const float C2 = SCALE * 1.4426950408889634f;   // SCALE * log2(e)
    const u32 ONES2 = 0x3C003C00u;                  // (1.0h, 1.0h)

    u32 kpA[2] = { smem_u32(KpB[0]), smem_u32(KpB[1]) };
    u32 vpA[2] = { smem_u32(VpB[0]), smem_u32(VpB[1]) };

    // issue copy group for tile kb into buffer buf
    auto issue = [&](int kb, int buf) {
        const u32* ks = g_Kp + ((size_t)(bh * 16 + kb)) * 4224;
        const u32* vs = g_Vp + ((size_t)(bh * 16 + kb)) * 4224;
        for (int i = tid; i < 1056; i += 256) {
            cpa16(kpA[buf] + (u32)(i << 4), ks + ((size_t)i << 2));
            cpa16(vpA[buf] + (u32)(i << 4), vs + ((size_t)i << 2));
        }
        CP_COMMIT();
    };

    issue(0, 0);

    // overlap: Q pack + T reduction while tile 0 streams in
    int rb = tid >> 4, c4 = (tid & 15) << 2;
#pragma unroll
    for (int it = 0; it < 8; it++) {
        int r = rb + (it << 4);
        float4 qv = *(const float4*)(Qb + (size_t)r * DIM + c4);
        qv.x *= C2; qv.y *= C2; qv.z *= C2; qv.w *= C2;
        stA16f(Qa, r, c4, qv);
    }
    if (tid < 64) {
        float s = 0.f;
        const float* tp = g_Tp + (size_t)bh * 1024 + tid;
#pragma unroll
        for (int kb = 0; kb < 16; kb++) s += tp[kb * 64];
        Tf[tid] = s;
    }

    float o[8][4];
#pragma unroll
    for (int nt = 0; nt < 8; nt++)
#pragma unroll
        for (int t = 0; t < 4; t++) o[nt][t] = 0.f;

    for (int kb = 0; kb < 16; kb++) {
        int cur = kb & 1;
        CP_WAIT0();            // tile kb landed (sole pending group)
        __syncthreads();       // visibility + all reads of buf[cur^1] done
        if (kb < 15) issue(kb + 1, cur ^ 1);   // stream next while computing

        const u32* Kp = KpB[cur];
        const u32* Vp = VpB[cur];

#pragma unroll
        for (int half = 0; half < 2; half++) {
            float acc[8][4];
#pragma unroll
            for (int nt = 0; nt < 8; nt++)
#pragma unroll
                for (int tt = 0; tt < 4; tt++) acc[nt][tt] = 0.f;
#pragma unroll
            for (int ks = 0; ks < 4; ks++) {
                uint4 a = ldA16(Qa, ks, w, lane);
#pragma unroll
                for (int nt = 0; nt < 8; nt++) {
                    uint2 bf = ldB16<16>(Kp, ks, half * 8 + nt, lane);
                    mma16f(acc[nt], a, bf);
                }
            }

#pragma unroll
            for (int j2 = 0; j2 < 4; j2++) {
                uint4 ah;
                ah.x = hsubx2(ex2h2(f16x2_rn(acc[2 * j2][1], acc[2 * j2][0])), ONES2);
                ah.y = hsubx2(ex2h2(f16x2_rn(acc[2 * j2][3], acc[2 * j2][2])), ONES2);
                ah.z = hsubx2(ex2h2(f16x2_rn(acc[2 * j2 + 1][1], acc[2 * j2 + 1][0])), ONES2);
                ah.w = hsubx2(ex2h2(f16x2_rn(acc[2 * j2 + 1][3], acc[2 * j2 + 1][2])), ONES2);
                int ks2 = half * 4 + j2;
#pragma unroll
                for (int nt = 0; nt < 8; nt++) {
                    uint2 bv = ldB16<8>(Vp, ks2, nt, lane);
                    mma16f(o[nt], ah, bv);
                }
            }
        }
    }

    const float inv1024 = 1.0f / 1024.0f;
    int r = lane >> 2, c2 = (lane & 3) << 1;
    float* obase = g_att + ((size_t)b * SEQ + q0 + 16 * w + r) * DIM + h * HD;
#pragma unroll
    for (int nt = 0; nt < 8; nt++) {
        int d0 = nt * 8 + c2;
        float t0 = Tf[d0], t1 = Tf[d0 + 1];
        *(float2*)(obase + d0) =
            make_float2((o[nt][0] + t0) * inv1024, (o[nt][1] + t1) * inv1024);
        *(float2*)(obase + (size_t)8 * DIM + d0) =
            make_float2((o[nt][2] + t0) * inv1024, (o[nt][3] + t1) * inv1024);
    }
}

// ---------------------------------------------------------------------------
// Kernel 3: out = g_att @ W^T + b.  Single-pass fp16. (r12, proven)
// ---------------------------------------------------------------------------
__global__ void __launch_bounds__(256, 2) k3_linear(const float* __restrict__ Wg,
                                                    const float* __restrict__ bg,
                                                    float* __restrict__ Og) {
    extern __shared__ u32 smu[];
    u32* Xp = smu;             // fp16 A-pack : 4096 u32
    u32* Wp = smu + 4096;      // fp16 B-pack : 4224 u32

    int tid = threadIdx.x, lane = tid & 31, w = tid >> 5;
    int wm = w >> 2, wn = w & 3;
    int n0 = blockIdx.x << 7, m0 = blockIdx.y << 7;

    float acc[4][4][4];
#pragma unroll
    for (int i = 0; i < 4; i++)
#pragma unroll
        for (int j = 0; j < 4; j++)
#pragma unroll
            for (int t = 0; t < 4; t++) acc[i][j][t] = 0.f;

    int rb = tid >> 4, c4 = (tid & 15) << 2;
    for (int d0 = 0; d0 < DIM; d0 += 64) {
        __syncthreads();
#pragma unroll
        for (int it = 0; it < 8; it++) {
            int r = rb + (it << 4);
            stA16f(Xp, r, c4,
                   *(const float4*)(g_att + (size_t)(m0 + r) * DIM + d0 + c4));
            stB16f<16>(Wp, r, c4,
                       *(const float4*)(Wg + (size_t)(n0 + r) * DIM + d0 + c4));
        }
        __syncthreads();

#pragma unroll
        for (int ks = 0; ks < 4; ks++) {
            uint4 ah[4]; uint2 bh[4];
#pragma unroll
            for (int i = 0; i < 4; i++) ah[i] = ldA16(Xp, ks, wm * 4 + i, lane);
#pragma unroll
            for (int j = 0; j < 4; j++) bh[j] = ldB16<16>(Wp, ks, wn * 4 + j, lane);
#pragma unroll
            for (int i = 0; i < 4; i++)
#pragma unroll
                for (int j = 0; j < 4; j++)
                    mma16f(acc[i][j], ah[i], bh[j]);
        }
    }

#pragma unroll
    for (int i = 0; i < 4; i++)
#pragma unroll
        for (int j = 0; j < 4; j++) {
            int r = wm * 64 + i * 16 + (lane >> 2);
            int n = wn * 32 + j * 8 + ((lane & 3) << 1);
            float2 bb = *(const float2*)(bg + n0 + n);
            float* p = Og + (size_t)(m0 + r) * DIM + n0 + n;
            *(float2*)p = make_float2(acc[i][j][0] + bb.x, acc[i][j][1] + bb.y);
            *(float2*)(p + (size_t)8 * DIM) =
                make_float2(acc[i][j][2] + bb.x, acc[i][j][3] + bb.y);
        }
}

// ---------------------------------------------------------------------------

extern "C" void kernel_launch(void* const* d_in, const int* in_sizes, int n_in,
                              void* d_out, int out_size) {
    const float* Q = (const float*)d_in[0];
    const float* K = (const float*)d_in[1];
    const float* V = (const float*)d_in[2];
    const float* W = (const float*)d_in[3];
    const float* bias = (const float*)d_in[4];
    float* out = (float*)d_out;
    (void)in_sizes; (void)n_in; (void)out_size;

    const int smem1 = 12672 * 4;   // 50688
    const int smem2 = 21056 * 4;   // 84224
    const int smem3 = 8320 * 4;    // 33280

    cudaFuncSetAttribute(k1_colsum, cudaFuncAttributeMaxDynamicSharedMemorySize, smem1);
    cudaFuncSetAttribute(k2_attnv,  cudaFuncAttributeMaxDynamicSharedMemorySize, smem2);
    cudaFuncSetAttribute(k3_linear, cudaFuncAttributeMaxDynamicSharedMemorySize, smem3);

    dim3 gAttn(SEQ / 128, NH, NB);          // 1024 CTAs
    k1_colsum<<<gAttn, 256, smem1>>>(Q, K, V);
    k2_attnv<<<gAttn, 256, smem2>>>(Q);

    dim3 gLin(DIM / 128, (NB * SEQ) / 128); // 512 CTAs
    k3_linear<<<gLin, 256, smem3>>>(W, bias, out);
}